// round 3
// baseline (speedup 1.0000x reference)
#include <cuda_runtime.h>
#include <cuda_bf16.h>

// Problem constants (fixed shapes per reference setup_inputs)
#define BQ    8      // batch
#define BSZ   16     // block_size
#define MAXB  128    // max blocks per seq
#define NH    8      // kv heads
#define HD    128    // head dim
#define NTOT  2048   // total physical blocks
// float4 counts
#define HALF4 (NTOT * NH * BSZ * (HD / 4))   // 8,388,608 float4 per cache tensor

// Single fused kernel. Each CTA covers 256 consecutive output float4s of the
// K tensor (plus their V twins at +HALF4), which all live inside ONE physical
// block (4096 float4 per block, 16 CTAs per block). The CTA first computes
// that block's owner via a cooperative scan of all 1024 (b, slot) pairs,
// reproducing the reference's tail-pop free-list allocation; table loads are
// L1/L2 hits (12 KB of tables, hot after the first wave). Then the bulk copy:
// one warp covers a (blk, h, off) row of 128 floats in each tensor, so the
// source-select branch is warp-uniform and every access is a coalesced
// 128-bit op. Streaming hints keep the 512 MB one-pass stream out of L2.
__global__ void __launch_bounds__(256, 8)
fused_paged_kv_kernel(const float4* __restrict__ keys,
                      const float4* __restrict__ vals,
                      const float4* __restrict__ kc,
                      const float4* __restrict__ vc,
                      const int* __restrict__ seq_lens,
                      const int* __restrict__ input_len,
                      const int* __restrict__ cu_seqlens,
                      const int* __restrict__ block_tables,
                      const int* __restrict__ free_blocks,
                      int num_free,
                      float4* __restrict__ out) {
    __shared__ int s_owner;    // candidate index c = b*MAXB + slot, or -1
    __shared__ int s_t0;       // new-token index at off=0: slot*BSZ - seq_lens[b]
    __shared__ int s_il;       // input_len[b]
    __shared__ int s_tokbase;  // cu_seqlens[b]

    int tid = threadIdx.x;
    if (tid == 0) s_owner = -1;
    __syncthreads();

    int i   = blockIdx.x * 256 + tid;   // 0 .. HALF4-1
    int blk = i >> 12;                  // physical block this CTA serves

    // ---- cooperative owner scan: 256 threads x 4 candidates = all (b,slot) ----
    #pragma unroll
    for (int k = 0; k < 4; k++) {
        int c    = tid + k * 256;
        int b    = c >> 7;              // / MAXB
        int slot = c & (MAXB - 1);
        int sl   = seq_lens[b];
        int il   = input_len[b];
        if (il > 0) {
            int first = sl / BSZ;
            int last  = (sl + il - 1) / BSZ;
            if (slot >= first && slot <= last) {
                int old_nb = (sl + BSZ - 1) / BSZ;
                int new_nb = (sl + il + BSZ - 1) / BSZ;
                int bt;
                if (slot >= old_nb && slot < new_nb) {
                    // tail-pop free-list allocation, as in the reference
                    int cum = 0;
                    for (int j = 0; j <= b; j++) {
                        int s = seq_lens[j], l = input_len[j];
                        cum += (s + l + BSZ - 1) / BSZ - (s + BSZ - 1) / BSZ;
                    }
                    int fi = num_free - cum + (slot - old_nb);
                    fi = max(0, min(fi, num_free - 1));
                    bt = free_blocks[fi];
                } else {
                    bt = block_tables[b * MAXB + slot];
                }
                if (bt == blk) {
                    s_owner   = c;
                    s_t0      = slot * BSZ - sl;
                    s_il      = il;
                    s_tokbase = cu_seqlens[b];
                }
            }
        }
    }
    __syncthreads();

    // ---- bulk copy / scatter-select ----
    int d4  = i & 31;
    int off = (i >> 5) & 15;
    int h   = (i >> 9) & 7;

    float4 kv, vv;
    bool from_new = false;
    if (s_owner >= 0) {
        int t = s_t0 + off;             // new-token index for this row
        if (t >= 0 && t < s_il) {
            int tok  = s_tokbase + t;
            int src4 = (tok * NH + h) * (HD / 4) + d4;
            kv = __ldcs(keys + src4);
            vv = __ldcs(vals + src4);
            from_new = true;
        }
    }
    if (!from_new) {
        kv = __ldcs(kc + i);
        vv = __ldcs(vc + i);
    }

    __stcs(out + i,         kv);
    __stcs(out + i + HALF4, vv);
}

extern "C" void kernel_launch(void* const* d_in, const int* in_sizes, int n_in,
                              void* d_out, int out_size) {
    // metadata order:
    // 0: layer_idx (unused)
    // 1: key_states   [B*L, H, D] f32
    // 2: value_states [B*L, H, D] f32
    // 3: input_len    [B] i32
    // 4: cu_seqlens   [B+1] i32
    // 5: k_cache      [TOTAL, H, BS, D] f32
    // 6: v_cache      [TOTAL, H, BS, D] f32
    // 7: block_tables [B, MAXB] i32
    // 8: seq_lens     [B] i32
    // 9: free_blocks  [TOTAL] i32
    const float4* keys        = (const float4*)d_in[1];
    const float4* vals        = (const float4*)d_in[2];
    const int*    input_len   = (const int*)d_in[3];
    const int*    cu_seqlens  = (const int*)d_in[4];
    const float4* kc          = (const float4*)d_in[5];
    const float4* vc          = (const float4*)d_in[6];
    const int*    block_tbl   = (const int*)d_in[7];
    const int*    seq_lens    = (const int*)d_in[8];
    const int*    free_blocks = (const int*)d_in[9];
    int num_free = in_sizes[9];

    float4* out = (float4*)d_out;

    fused_paged_kv_kernel<<<HALF4 / 256, 256>>>(
        keys, vals, kc, vc, seq_lens, input_len, cu_seqlens,
        block_tbl, free_blocks, num_free, out);
}

// round 7
// speedup vs baseline: 1.1245x; 1.1245x over previous
#include <cuda_runtime.h>
#include <cuda_bf16.h>

// Problem constants (fixed shapes per reference setup_inputs)
#define BQ    8      // batch
#define BSZ   16     // block_size
#define MAXB  128    // max blocks per seq
#define NH    8      // kv heads
#define HD    128    // head dim
#define NTOT  2048   // total physical blocks
// float4 counts
#define HALF4 (NTOT * NH * BSZ * (HD / 4))   // 8,388,608 float4 per cache tensor

// Inverse map: physical block -> (b * MAXB + slot), or -1 if untouched.
__device__ int g_owner[NTOT];

// Single-block fused prologue: init the owner map, then reproduce the
// reference's tail-pop free-list allocation and mark ownership for every
// slot whose block receives at least one new token.
__global__ void __launch_bounds__(1024, 1)
prologue_kernel(const int* __restrict__ seq_lens,
                const int* __restrict__ input_len,
                const int* __restrict__ block_tables,
                const int* __restrict__ free_blocks,
                int num_free) {
    int tid = threadIdx.x;            // 0..1023
    g_owner[tid]        = -1;
    g_owner[tid + 1024] = -1;
    __syncthreads();

    // One thread per (b, slot): BQ * MAXB = 1024 exactly.
    int b    = tid >> 7;              // / MAXB
    int slot = tid & (MAXB - 1);

    int sl = seq_lens[b];
    int il = input_len[b];
    int old_nb = (sl + BSZ - 1) / BSZ;
    int new_nb = (sl + il + BSZ - 1) / BSZ;

    int cum = 0;
    for (int j = 0; j <= b; j++) {
        int s = seq_lens[j], l = input_len[j];
        cum += (s + l + BSZ - 1) / BSZ - (s + BSZ - 1) / BSZ;
    }
    int start = num_free - cum;

    int bt;
    if (slot >= old_nb && slot < new_nb) {
        int fi = start + (slot - old_nb);
        fi = max(0, min(fi, num_free - 1));
        bt = free_blocks[fi];
    } else {
        bt = block_tables[b * MAXB + slot];
    }

    if (il > 0) {
        int first = sl / BSZ;
        int last  = (sl + il - 1) / BSZ;
        if (slot >= first && slot <= last) {
            g_owner[bt] = b * MAXB + slot;
        }
    }
}

// Each CTA covers 512 consecutive K float4s (and their V twins at +HALF4),
// all inside ONE physical block (4096 float4/block, 512 | 4096). Each thread
// handles two coalesced float4s per tensor (i and i+256): 4 independent 16B
// loads + 4 stores = MLP 4, half the grid and half the index math of the
// one-float4 version. The source-select branch is warp-uniform (a warp spans
// one 128-float row per group). Streaming hints keep the 512MB one-pass
// stream from thrashing L2.
__global__ void __launch_bounds__(256, 8)
scatter_copy_kernel(const float4* __restrict__ keys,
                    const float4* __restrict__ vals,
                    const float4* __restrict__ kc,
                    const float4* __restrict__ vc,
                    const int* __restrict__ seq_lens,
                    const int* __restrict__ input_len,
                    const int* __restrict__ cu_seqlens,
                    float4* __restrict__ out) {
    int tid = threadIdx.x;
    int i0  = blockIdx.x * 512 + tid;    // first float4 index
    int i1  = i0 + 256;                  // second (same physical block)
    int blk = i0 >> 12;

    int owner = g_owner[blk];

    // per-index row decode
    int d4a  = i0 & 31,            d4b  = i1 & 31;
    int offa = (i0 >> 5) & 15,     offb = (i1 >> 5) & 15;
    int ha   = (i0 >> 9) & 7,      hb   = (i1 >> 9) & 7;

    float4 k0, v0, k1, v1;
    bool na = false, nb = false;

    if (owner >= 0) {
        int b    = owner >> 7;           // / MAXB
        int slot = owner & (MAXB - 1);
        int sl   = seq_lens[b];
        int il   = input_len[b];
        int cs   = cu_seqlens[b];
        int base = slot * BSZ - sl;      // new-token index at off=0

        int ta = base + offa;
        if (ta >= 0 && ta < il) {
            int src = ((cs + ta) * NH + ha) * (HD / 4) + d4a;
            k0 = __ldcs(keys + src);
            v0 = __ldcs(vals + src);
            na = true;
        }
        int tb = base + offb;
        if (tb >= 0 && tb < il) {
            int src = ((cs + tb) * NH + hb) * (HD / 4) + d4b;
            k1 = __ldcs(keys + src);
            v1 = __ldcs(vals + src);
            nb = true;
        }
    }
    if (!na) { k0 = __ldcs(kc + i0); v0 = __ldcs(vc + i0); }
    if (!nb) { k1 = __ldcs(kc + i1); v1 = __ldcs(vc + i1); }

    __stcs(out + i0,         k0);
    __stcs(out + i1,         k1);
    __stcs(out + i0 + HALF4, v0);
    __stcs(out + i1 + HALF4, v1);
}

extern "C" void kernel_launch(void* const* d_in, const int* in_sizes, int n_in,
                              void* d_out, int out_size) {
    // metadata order:
    // 0: layer_idx (unused)
    // 1: key_states   [B*L, H, D] f32
    // 2: value_states [B*L, H, D] f32
    // 3: input_len    [B] i32
    // 4: cu_seqlens   [B+1] i32
    // 5: k_cache      [TOTAL, H, BS, D] f32
    // 6: v_cache      [TOTAL, H, BS, D] f32
    // 7: block_tables [B, MAXB] i32
    // 8: seq_lens     [B] i32
    // 9: free_blocks  [TOTAL] i32
    const float4* keys        = (const float4*)d_in[1];
    const float4* vals        = (const float4*)d_in[2];
    const int*    input_len   = (const int*)d_in[3];
    const int*    cu_seqlens  = (const int*)d_in[4];
    const float4* kc          = (const float4*)d_in[5];
    const float4* vc          = (const float4*)d_in[6];
    const int*    block_tbl   = (const int*)d_in[7];
    const int*    seq_lens    = (const int*)d_in[8];
    const int*    free_blocks = (const int*)d_in[9];
    int num_free = in_sizes[9];

    float4* out = (float4*)d_out;

    prologue_kernel<<<1, 1024>>>(seq_lens, input_len, block_tbl,
                                 free_blocks, num_free);
    scatter_copy_kernel<<<HALF4 / 512, 256>>>(
        keys, vals, kc, vc, seq_lens, input_len, cu_seqlens, out);
}